// round 10
// baseline (speedup 1.0000x reference)
#include <cuda_runtime.h>
#include <cuda_fp16.h>
#include <math.h>

#define NV_MAX   1048576
#define MAX_SEG  50000
#define D        12
#define ROW_PAD  16          // halves per padded row = 32 bytes = 1 L2 sector
#define EPS      1e-12f
#define CHUNK    1024        // seg-id staging tile (4KB smem)
#define VPB      64          // voxels per block (4 lanes per voxel)

__device__ int g_start[NV_MAX];
__device__ int g_end[NV_MAX];
__device__ __align__(32) __half g_tab[MAX_SEG * ROW_PAD];

// Fused prep: blocks [0, bblocks) find run boundaries (4 tokens/thread, with
// gap-fill so bounds are monotone/contiguous); remaining blocks repack table.
__global__ __launch_bounds__(256) void k_prep(const int*   __restrict__ vox,
                                              const float* __restrict__ table,
                                              int T, int n_voxels,
                                              int rows, int bblocks) {
    if (blockIdx.x < (unsigned)bblocks) {
        int i = blockIdx.x * 256 + threadIdx.x;
        int base = i * 4;
        if (base >= T) return;

        int4 q = __ldg((const int4*)vox + i);
        int vals[5];
        vals[0] = q.x; vals[1] = q.y; vals[2] = q.z; vals[3] = q.w;
        vals[4] = (base + 4 >= T) ? -1 : __ldg(vox + base + 4);

        if (base == 0) {
            for (int w = 0; w < vals[0]; w++) { g_start[w] = 0; g_end[w] = 0; }
            g_start[vals[0]] = 0;
        }
#pragma unroll
        for (int j = 0; j < 4; j++) {
            int idx = base + j;
            int cur = vals[j];
            if (idx == T - 1) {
                g_end[cur] = T;
                for (int w = cur + 1; w < n_voxels; w++) { g_start[w] = T; g_end[w] = T; }
            } else {
                int nx = vals[j + 1];
                if (nx != cur) {
                    g_end[cur]  = idx + 1;
                    g_start[nx] = idx + 1;
                    for (int w = cur + 1; w < nx; w++) { g_start[w] = idx + 1; g_end[w] = idx + 1; }
                }
            }
        }
    } else {
        int r = (blockIdx.x - bblocks) * 256 + threadIdx.x;
        if (r >= rows) return;
        const float4* src = (const float4*)(table + (size_t)r * D);
        float4 a = __ldg(src + 0);
        float4 b = __ldg(src + 1);
        float4 c = __ldg(src + 2);
        __half2 h[8];
        h[0] = __floats2half2_rn(a.x, a.y);
        h[1] = __floats2half2_rn(a.z, a.w);
        h[2] = __floats2half2_rn(b.x, b.y);
        h[3] = __floats2half2_rn(b.z, b.w);
        h[4] = __floats2half2_rn(c.x, c.y);
        h[5] = __floats2half2_rn(c.z, c.w);
        h[6] = __floats2half2_rn(0.f, 0.f);
        h[7] = __floats2half2_rn(0.f, 0.f);
        uint4* dst = (uint4*)(g_tab + (size_t)r * ROW_PAD);
        dst[0] = *(uint4*)&h[0];
        dst[1] = *(uint4*)&h[4];
    }
}

#define H2(u) (*(const __half2*)&(u))

__device__ __forceinline__ void acc8(float* acc, __half2 a, __half2 b,
                                     __half2 c, __half2 d) {
    float2 f;
    f = __half22float2(a); acc[0] += f.x; acc[1] += f.y;
    f = __half22float2(b); acc[2] += f.x; acc[3] += f.y;
    f = __half22float2(c); acc[4] += f.x; acc[5] += f.y;
    f = __half22float2(d); acc[6] += f.x; acc[7] += f.y;
}

// Quad-cooperative pool: lanes (4k..4k+3) share voxel k. Lane role:
// tok_off = (lane>>1)&1 selects even/odd token, p = lane&1 selects 16B row
// half. Each iteration consumes 4 tokens/quad (unroll 2 + fp16 pre-add).
// Warp-iteration skew: max8(ceil(Poisson(8)/4)) ~ 3.05 vs R7's 4.1.
__global__ __launch_bounds__(256) void k_pool(const int* __restrict__ seg,
                                              float*     __restrict__ out,
                                              int n_voxels) {
    __shared__ int s_seg[CHUNK];

    int tid     = threadIdx.x;
    int lane    = tid & 31;
    int p       = lane & 1;
    int tok_off = (lane >> 1) & 1;

    int v0 = blockIdx.x * VPB;
    int vL = min(v0 + VPB - 1, n_voxels - 1);
    int v  = v0 + (tid >> 5) * 8 + (lane >> 2);

    int rs = g_start[v0];
    int re = g_end[vL];

    int s, e;
    if (v < n_voxels) { s = g_start[v]; e = g_end[v]; }
    else              { s = rs;         e = rs;       }

    float acc[8];
#pragma unroll
    for (int d = 0; d < 8; d++) acc[d] = 0.0f;

    int t = s;
    for (int cbase = rs; cbase < re; cbase += CHUNK) {
        int clim = min(re, cbase + CHUNK);
        __syncthreads();
        for (int j = cbase + tid; j < clim; j += 256)
            s_seg[j - cbase] = __ldg(seg + j);
        __syncthreads();

        int e_c = min(e, clim);

        // main: 4 tokens/quad per iteration; this lane handles tokens
        // t+tok_off and t+tok_off+2 (its 16B half of each), fp16 pre-add.
        while (t + 3 < e_c) {
            int i0  = t - cbase + tok_off;
            int sg0 = s_seg[i0];
            int sg1 = s_seg[i0 + 2];
            uint4 q0 = __ldg((const uint4*)(g_tab + (size_t)sg0 * ROW_PAD) + p);
            uint4 q1 = __ldg((const uint4*)(g_tab + (size_t)sg1 * ROW_PAD) + p);
            __half2 a0 = __hadd2(H2(q0.x), H2(q1.x));
            __half2 a1 = __hadd2(H2(q0.y), H2(q1.y));
            __half2 a2 = __hadd2(H2(q0.z), H2(q1.z));
            __half2 a3 = __hadd2(H2(q0.w), H2(q1.w));
            acc8(acc, a0, a1, a2, a3);
            t += 4;
        }
        // tail: up to 3 tokens, 2 per step; t lands exactly on e_c.
        while (t < e_c) {
            int step = min(2, e_c - t);
            int tt = t + tok_off;
            if (tok_off < step) {
                int sg = s_seg[tt - cbase];
                uint4 q = __ldg((const uint4*)(g_tab + (size_t)sg * ROW_PAD) + p);
                acc8(acc, H2(q.x), H2(q.y), H2(q.z), H2(q.w));
            }
            t += step;
        }
    }

    // Epilogue: combine token-parity partners (xor 2), then halves (xor 1).
    __syncwarp();
#pragma unroll
    for (int d = 0; d < 8; d++)
        acc[d] += __shfl_xor_sync(0xFFFFFFFFu, acc[d], 2);

    int cnt = e - s;
    float invc = 1.0f / (float)(cnt > 0 ? cnt : 1);

    float m[8];
    float n2 = 0.0f;
#pragma unroll
    for (int d = 0; d < 8; d++) {
        m[d] = acc[d] * invc;
        n2 += m[d] * m[d];        // p==1 lanes: acc[4..7] are pad zeros
    }
    n2 += __shfl_xor_sync(0xFFFFFFFFu, n2, 1);
    float inv = 1.0f / fmaxf(sqrtf(n2), EPS);

    if (v < n_voxels && tok_off == 0) {
        float4* orow = (float4*)(out + (size_t)v * D);
        if (p == 0) {
            orow[0] = make_float4(m[0] * inv, m[1] * inv, m[2] * inv, m[3] * inv);
            orow[1] = make_float4(m[4] * inv, m[5] * inv, m[6] * inv, m[7] * inv);
        } else {
            orow[2] = make_float4(m[0] * inv, m[1] * inv, m[2] * inv, m[3] * inv);
        }
    }
}

extern "C" void kernel_launch(void* const* d_in, const int* in_sizes, int n_in,
                              void* d_out, int out_size) {
    const float* table = (const float*)d_in[0];
    const int*   seg   = (const int*)  d_in[1];
    const int*   vox   = (const int*)  d_in[2];
    float*       out   = (float*)      d_out;

    int rows     = in_sizes[0] / D;
    int T        = in_sizes[1];
    int n_voxels = out_size / D;

    int bblocks = (T / 4 + 255) / 256;
    int rblocks = (rows + 255) / 256;
    k_prep<<<bblocks + rblocks, 256>>>(vox, table, T, n_voxels, rows, bblocks);
    k_pool<<<(n_voxels + VPB - 1) / VPB, 256>>>(seg, out, n_voxels);
}

// round 11
// speedup vs baseline: 1.3617x; 1.3617x over previous
#include <cuda_runtime.h>
#include <cuda_fp16.h>
#include <math.h>

#define NV_MAX   1048576
#define MAX_SEG  50000
#define D        12
#define ROW_PAD  16          // halves per padded row = 32 bytes = 1 L2 sector
#define EPS      1e-12f
#define CHUNK    2048        // seg-id staging tile (8KB smem)
#define VPB      128         // voxels per block (2 lanes per voxel)

__device__ int g_start[NV_MAX];
__device__ int g_end[NV_MAX];
__device__ __align__(32) __half g_tab[MAX_SEG * ROW_PAD];

// Fused prep: blocks [0, bblocks) find run boundaries (4 tokens/thread, with
// gap-fill so bounds are monotone); remaining blocks repack the table to fp16.
__global__ __launch_bounds__(256) void k_prep(const int*   __restrict__ vox,
                                              const float* __restrict__ table,
                                              int T, int n_voxels,
                                              int rows, int bblocks) {
    if (blockIdx.x < (unsigned)bblocks) {
        int i = blockIdx.x * 256 + threadIdx.x;
        int base = i * 4;
        if (base >= T) return;

        int4 q = __ldg((const int4*)vox + i);
        int vals[5];
        vals[0] = q.x; vals[1] = q.y; vals[2] = q.z; vals[3] = q.w;
        vals[4] = (base + 4 >= T) ? -1 : __ldg(vox + base + 4);

        if (base == 0) {
            for (int w = 0; w < vals[0]; w++) { g_start[w] = 0; g_end[w] = 0; }
            g_start[vals[0]] = 0;
        }
#pragma unroll
        for (int j = 0; j < 4; j++) {
            int idx = base + j;
            int cur = vals[j];
            if (idx == T - 1) {
                g_end[cur] = T;
                for (int w = cur + 1; w < n_voxels; w++) { g_start[w] = T; g_end[w] = T; }
            } else {
                int nx = vals[j + 1];
                if (nx != cur) {
                    g_end[cur]  = idx + 1;
                    g_start[nx] = idx + 1;
                    for (int w = cur + 1; w < nx; w++) { g_start[w] = idx + 1; g_end[w] = idx + 1; }
                }
            }
        }
    } else {
        int r = (blockIdx.x - bblocks) * 256 + threadIdx.x;
        if (r >= rows) return;
        const float4* src = (const float4*)(table + (size_t)r * D);
        float4 a = __ldg(src + 0);
        float4 b = __ldg(src + 1);
        float4 c = __ldg(src + 2);
        __half2 h[8];
        h[0] = __floats2half2_rn(a.x, a.y);
        h[1] = __floats2half2_rn(a.z, a.w);
        h[2] = __floats2half2_rn(b.x, b.y);
        h[3] = __floats2half2_rn(b.z, b.w);
        h[4] = __floats2half2_rn(c.x, c.y);
        h[5] = __floats2half2_rn(c.z, c.w);
        h[6] = __floats2half2_rn(0.f, 0.f);
        h[7] = __floats2half2_rn(0.f, 0.f);
        uint4* dst = (uint4*)(g_tab + (size_t)r * ROW_PAD);
        dst[0] = *(uint4*)&h[0];
        dst[1] = *(uint4*)&h[4];
    }
}

#define H2(u) (*(const __half2*)&(u))

__device__ __forceinline__ void acc_half4(float* acc, __half2 a, __half2 b,
                                          __half2 c, __half2 d) {
    float2 f;
    f = __half22float2(a); acc[0] += f.x; acc[1] += f.y;
    f = __half22float2(b); acc[2] += f.x; acc[3] += f.y;
    f = __half22float2(c); acc[4] += f.x; acc[5] += f.y;
    f = __half22float2(d); acc[6] += f.x; acc[7] += f.y;
}

// Pair-cooperative pool (R7 layout): lanes (2k,2k+1) share voxel k; even lane
// handles dims 0-7, odd lane dims 8-11(+pad). 1 L1 wavefront per token.
// Unroll-2 + fp16 pair pre-add; __launch_bounds__(256,8) -> 32 regs ->
// 8 CTAs/SM (64 warps) to hide gather latency and warp skew.
__global__ __launch_bounds__(256, 8) void k_pool(const int* __restrict__ seg,
                                                 float*     __restrict__ out,
                                                 int n_voxels) {
    __shared__ int s_seg[CHUNK];

    int tid = threadIdx.x;
    int p   = tid & 1;
    int v   = blockIdx.x * VPB + (tid >> 1);
    int v0  = blockIdx.x * VPB;
    int vL  = min(v0 + VPB - 1, n_voxels - 1);
    unsigned pairmask = 0x3u << ((tid & 31) & ~1);

    int rs = g_start[v0];
    int re = g_end[vL];

    int s, e;
    if (v < n_voxels) { s = g_start[v]; e = g_end[v]; }
    else              { s = rs;         e = rs;       }

    float acc[8];
#pragma unroll
    for (int d = 0; d < 8; d++) acc[d] = 0.0f;

    for (int cbase = rs; cbase < re; cbase += CHUNK) {
        int clim = min(re, cbase + CHUNK);
        __syncthreads();
        for (int j = cbase + tid; j < clim; j += 256)
            s_seg[j - cbase] = __ldg(seg + j);
        __syncthreads();

        int t0 = max(s, cbase);
        int t1 = min(e, clim);
        int t  = t0;

        // unroll-2: 2 loads in flight, fp16 pre-add of the token pair
        for (; t + 1 < t1; t += 2) {
            int i0 = t - cbase;
            int sg0 = s_seg[i0];
            int sg1 = s_seg[i0 + 1];
            uint4 q0 = __ldg((const uint4*)(g_tab + (size_t)sg0 * ROW_PAD) + p);
            uint4 q1 = __ldg((const uint4*)(g_tab + (size_t)sg1 * ROW_PAD) + p);

            __half2 a0 = __hadd2(H2(q0.x), H2(q1.x));
            __half2 a1 = __hadd2(H2(q0.y), H2(q1.y));
            __half2 a2 = __hadd2(H2(q0.z), H2(q1.z));
            __half2 a3 = __hadd2(H2(q0.w), H2(q1.w));
            acc_half4(acc, a0, a1, a2, a3);
        }
        if (t < t1) {
            int sg = s_seg[t - cbase];
            uint4 q = __ldg((const uint4*)(g_tab + (size_t)sg * ROW_PAD) + p);
            acc_half4(acc, H2(q.x), H2(q.y), H2(q.z), H2(q.w));
        }
    }

    int cnt = e - s;
    float invc = 1.0f / (float)(cnt > 0 ? cnt : 1);

    float m[8];
    float n2p = 0.0f;
    int nd = p ? 4 : 8;
#pragma unroll
    for (int d = 0; d < 8; d++) {
        m[d] = acc[d] * invc;
        if (d < nd) n2p += m[d] * m[d];
    }
    float norm2 = n2p + __shfl_xor_sync(0xFFFFFFFFu, n2p, 1);
    float inv   = 1.0f / fmaxf(sqrtf(norm2), EPS);

    if (v < n_voxels) {
        float4* orow = (float4*)(out + (size_t)v * D);
        if (p == 0) {
            orow[0] = make_float4(m[0] * inv, m[1] * inv, m[2] * inv, m[3] * inv);
            orow[1] = make_float4(m[4] * inv, m[5] * inv, m[6] * inv, m[7] * inv);
        } else {
            orow[2] = make_float4(m[0] * inv, m[1] * inv, m[2] * inv, m[3] * inv);
        }
    }
}

extern "C" void kernel_launch(void* const* d_in, const int* in_sizes, int n_in,
                              void* d_out, int out_size) {
    const float* table = (const float*)d_in[0];
    const int*   seg   = (const int*)  d_in[1];
    const int*   vox   = (const int*)  d_in[2];
    float*       out   = (float*)      d_out;

    int rows     = in_sizes[0] / D;
    int T        = in_sizes[1];
    int n_voxels = out_size / D;

    int bblocks = (T / 4 + 255) / 256;
    int rblocks = (rows + 255) / 256;
    k_prep<<<bblocks + rblocks, 256>>>(vox, table, T, n_voxels, rows, bblocks);
    k_pool<<<(n_voxels + VPB - 1) / VPB, 256>>>(seg, out, n_voxels);
}